// round 14
// baseline (speedup 1.0000x reference)
#include <cuda_runtime.h>
#include <math.h>

// Problem: B=64, V=8, J=17, H=256
// keypoints_gt: (B,V,J,2) float32   -> d_in[0], 17408 elems
// heatmap:      (B,V,1,H,H) float32 -> d_in[1], 33554432 elems
// out: scalar float = mean over B*V*J of -log(hm[b,v, clip(ceil(ky)), clip(ceil(kx))])
//
// Single-atomic-word design:
//   - workers: 272 single-warp CTAs; per-thread -log converted to fixed-point
//     u32 (scale 2^23); warp-summed with ONE redux.sync.add.u32; lane 0 fires
//     ONE atomicAdd(u64) of (1<<48 | warp_sum): count in high 16 bits,
//     payload in low 48 bits. Arrival signal and data share one atomic word
//     -> no fences, no ordering, no partials array.
//   - poller: block 0 thread 0 polls the one u64 until count==272, converts
//     in double, writes the scalar, resets the word for the next replay.
//   - determinism: integer adds are associative -> bit-exact every replay.
//   - precision: quant error <= 2^-24 rel/value; sum < 2^40 fits 48 bits.

#define NTOT   8704      // 64*8*17
#define JDIM   17
#define HDIM   256
#define NWRK   272       // worker blocks 1..272: 272 * 32 = 8704 exactly
#define NBLK   (NWRK + 1)
#define NTHR   32
#define FXSCALE 8388608.0f   // 2^23

__device__ unsigned long long g_acc;   // zero-init at load; poller resets each call

__device__ __forceinline__ unsigned long long ld_relaxed_u64(const unsigned long long* p) {
    unsigned long long v;
    asm volatile("ld.relaxed.gpu.global.u64 %0, [%1];" : "=l"(v) : "l"(p) : "memory");
    return v;
}
__device__ __forceinline__ void st_relaxed_u64(unsigned long long* p, unsigned long long v) {
    asm volatile("st.relaxed.gpu.global.u64 [%0], %1;" :: "l"(p), "l"(v) : "memory");
}
__device__ __forceinline__ unsigned int redux_add_u32(unsigned int v) {
    unsigned int r;
    asm volatile("redux.sync.add.u32 %0, %1, 0xFFFFFFFF;" : "=r"(r) : "r"(v));
    return r;
}

__global__ __launch_bounds__(NTHR) void heatmap_ce_fused_kernel(
    const float* __restrict__ kp,   // (NTOT, 2)
    const float* __restrict__ hm,   // (B*V, H, H)
    float* __restrict__ out)
{
    const int lane = threadIdx.x;                     // block == warp

    if (blockIdx.x != 0) {
        // ---------------- worker path: fully uniform ----------------
        const int i = (blockIdx.x - 1) * NTHR + lane; // 0..8703, exact

        // kp-independent base, overlaps kp load latency.
        // Max offset 64*8*65536 = 33.5M < 2^31 -> 32-bit address math.
        const int base = (i / JDIM) * (HDIM * HDIM);  // bv * 65536

        const float2 k = reinterpret_cast<const float2*>(kp)[i];

        int xi = (int)ceilf(k.x);
        int yi = (int)ceilf(k.y);
        xi = min(max(xi, 0), HDIM - 1);
        yi = min(max(yi, 0), HDIM - 1);
        const int off = base + (yi << 8) + xi;

        const float val = __ldg(hm + off);
        const float s = -__logf(val);   // in (0, ~6.91]; fast log within 1e-3 tol

        // fixed-point: s * 2^23 < 2^26; warp sum < 2^31 -> u32 safe
        const unsigned int fx = __float2uint_rn(s * FXSCALE);

        // one-instruction warp reduction (replaces 5 SHFL levels)
        const unsigned int wsum = redux_add_u32(fx);

        if (lane == 0)
            atomicAdd(&g_acc, (1ULL << 48) | (unsigned long long)wsum);
        return;
    }

    // ------------- poller (block 0): one word, no fences -------------
    if (lane == 0) {
        unsigned long long v;
        do {
            v = ld_relaxed_u64(&g_acc);
        } while ((v >> 48) != (unsigned long long)NWRK);

        const unsigned long long sum_fx = v & 0xFFFFFFFFFFFFULL;   // low 48 bits
        const double mean = (double)sum_fx * (1.0 / ((double)FXSCALE * (double)NTOT));
        out[0] = (float)mean;

        st_relaxed_u64(&g_acc, 0ULL);    // rearm for next graph replay
    }
}

extern "C" void kernel_launch(void* const* d_in, const int* in_sizes, int n_in,
                              void* d_out, int out_size)
{
    const float* kp = (const float*)d_in[0];
    const float* hm = (const float*)d_in[1];
    float* out = (float*)d_out;

    heatmap_ce_fused_kernel<<<NBLK, NTHR>>>(kp, hm, out);
}